// round 13
// baseline (speedup 1.0000x reference)
#include <cuda_runtime.h>
#include <math.h>
#include <stdint.h>

#define BATCH   128
#define TT      504
#define TF      502      // tokens after features[:,2:]
#define TC      500      // cond frames
#define NSTEP   2000
#define NT      512      // threads in scan CTA

// ---------------- transposed-weight offsets (floats) ----------------
#define OFF_FWC    0          // (192,328)
#define OFF_FWCG   62976      // (192,192)
#define OFF_G1IH   99840      // (480,272)
#define OFF_G1HH   230400     // (480,160)
#define OFF_GLU1   307200     // (160,160)
#define OFF_G2IH   332800     // (384,240)
#define OFF_G2HH   424960     // (384,128)
#define OFF_GLU2   474112     // (128,128)
#define OFF_G3IH   490496     // (384,208)
#define OFF_G3HH   570368     // (384,128)
#define OFF_GLU3   619520     // (128,128)
#define OFF_SKIP   635904     // (128,688)
#define OFF_SKIPG  723968     // (128,128)
#define OFF_SIG    740352     // (40,128)
#define OFF_GOUT   745472     // (4,192)
#define WT_TOTAL   746240

// ---------------- device scratch ----------------
__device__ float g_x[BATCH * TF * 64];        // fd1 output
__device__ float g_y[BATCH * TC * 128];       // conv output
__device__ float g_cond[BATCH * TC * 320];    // fd2 output
__device__ float g_gain[NSTEP * BATCH];       // precomputed gains
__device__ float g_wt[WT_TOTAL];              // transposed weights [in][out]

__device__ __forceinline__ float sigf(float x) { return 1.0f / (1.0f + expf(-x)); }

// ---------------- cluster helpers ----------------
__device__ __forceinline__ uint32_t su32(const void* p) {
    return (uint32_t)__cvta_generic_to_shared(p);
}
__device__ __forceinline__ void st_peer(uint32_t laddr, float v, uint32_t prank) {
    uint32_t pa;
    asm volatile("mapa.shared::cluster.u32 %0, %1, %2;" : "=r"(pa) : "r"(laddr), "r"(prank));
    asm volatile("st.shared::cluster.f32 [%0], %1;" :: "r"(pa), "f"(v) : "memory");
}
#define CLUSTER_SYNC() do { \
    asm volatile("barrier.cluster.arrive.aligned;" ::: "memory"); \
    asm volatile("barrier.cluster.wait.aligned;" ::: "memory"); \
} while (0)

// ---------------- fused weight transpose: Wt[k*out+o] = W[o*in+k] ----------------
struct WP { const float* p[15]; };
__constant__ int T_OFF[15] = {OFF_FWC, OFF_FWCG, OFF_G1IH, OFF_G1HH, OFF_GLU1,
                              OFF_G2IH, OFF_G2HH, OFF_GLU2, OFF_G3IH, OFF_G3HH,
                              OFF_GLU3, OFF_SKIP, OFF_SKIPG, OFF_SIG, OFF_GOUT};
__constant__ int T_OUT[15] = {192, 192, 480, 480, 160, 384, 384, 128, 384, 384, 128, 128, 128, 40, 4};
__constant__ int T_IN [15] = {328, 192, 272, 160, 160, 240, 128, 128, 208, 128, 128, 688, 128, 128, 192};

__global__ void k_transpose_all(WP wp) {
    int l = blockIdx.y;
    int i = blockIdx.x * blockDim.x + threadIdx.x;
    int out = T_OUT[l], in = T_IN[l];
    if (i < out * in) {
        int o = i / in, k = i - o * in;
        g_wt[T_OFF[l] + k * out + o] = wp.p[l][i];
    }
}

// ---------------- fd1: weight-stationary, 1 block per batch elem ----------------
__global__ void k_fd1n(const float* __restrict__ feat, const int* __restrict__ period,
                       const float* __restrict__ pembed, const float* __restrict__ fd1) {
    int b = blockIdx.x;
    __shared__ float wd1[64 * 33];   // padded stride 33 -> conflict-free
    int tid = threadIdx.x;           // 256
    for (int i = tid; i < 64 * 32; i += 256) {
        int o = i >> 5, k = i & 31;
        wd1[o * 33 + k] = fd1[i];
    }
    __syncthreads();
    int warp = tid >> 5, lane = tid & 31;
    for (int t = warp; t < TF; t += 8) {
        int per = period[b * TT + t + 2];
        per = min(max(per, 32), 254);
        float v;
        if (lane < 20) v = feat[(b * TT + t + 2) * 20 + lane];
        else           v = pembed[(per - 32) * 12 + (lane - 20)];
        float a0 = 0.0f, a1 = 0.0f;
#pragma unroll
        for (int k = 0; k < 32; k++) {
            float xk = __shfl_sync(0xffffffffu, v, k);
            a0 = fmaf(wd1[lane * 33 + k], xk, a0);
            a1 = fmaf(wd1[(lane + 32) * 33 + k], xk, a1);
        }
        g_x[(b * TF + t) * 64 + lane] = tanhf(a0);
        g_x[(b * TF + t) * 64 + lane + 32] = tanhf(a1);
    }
}

// ---------------- conv1d: weight-stationary, 2 blocks per batch elem ----------------
#define CONV_SMEM ((128 * 193 + 192) * 4)
__global__ void k_convn(const float* __restrict__ wconv) {
    int b = blockIdx.x;
    int t0 = blockIdx.y * 250;
    extern __shared__ float smc[];
    float* wc = smc;                 // 128 x 193 (padded)
    float* xin = smc + 128 * 193;    // 192
    int tid = threadIdx.x;           // 128
    for (int i = tid; i < 128 * 192; i += 128) {
        int oc = i / 192, k = i - oc * 192;
        wc[oc * 193 + k] = wconv[i];
    }
    __syncthreads();
    for (int t = t0; t < t0 + 250; t++) {
        for (int i = tid; i < 192; i += 128)
            xin[i] = g_x[(b * TF + t + (i >> 6)) * 64 + (i & 63)];
        __syncthreads();
        float acc = 0.0f;
        const float* w = wc + tid * 193;
#pragma unroll 8
        for (int ic = 0; ic < 64; ic++) {
            acc = fmaf(w[ic * 3 + 0], xin[ic], acc);
            acc = fmaf(w[ic * 3 + 1], xin[64 + ic], acc);
            acc = fmaf(w[ic * 3 + 2], xin[128 + ic], acc);
        }
        g_y[(b * TC + t) * 128 + tid] = tanhf(acc);
        __syncthreads();
    }
}

// ---------------- fd2 + gains: weight-stationary, 1 block per batch elem ----------------
#define FD2_SMEM ((320 * 129 + 128 + 320 + 80) * 4)
__global__ void k_fd2n(const float* __restrict__ fd2, const float* __restrict__ cg_w,
                       const float* __restrict__ cg_b) {
    int b = blockIdx.x;
    extern __shared__ float smf[];
    float* wf = smf;                       // 320 x 129 (padded)
    float* ybuf = wf + 320 * 129;          // 128
    float* condb = ybuf + 128;             // 320
    float* cgw = condb + 320;              // 80
    int tid = threadIdx.x;                 // 320
    for (int i = tid; i < 320 * 128; i += 320) {
        int o = i >> 7, k = i & 127;
        wf[o * 129 + k] = fd2[i];
    }
    if (tid < 80) cgw[tid] = cg_w[tid];
    __syncthreads();
    float cb = cg_b[0];
    for (int t = 0; t < TC; t++) {
        if (tid < 128) ybuf[tid] = g_y[(b * TC + t) * 128 + tid];
        __syncthreads();
        float acc = 0.0f;
        const float* w = wf + tid * 129;
#pragma unroll 8
        for (int k = 0; k < 128; k++) acc = fmaf(w[k], ybuf[k], acc);
        float cv = tanhf(acc);
        condb[tid] = cv;
        g_cond[((size_t)(b * TC + t)) * 320 + tid] = cv;
        __syncthreads();
        if (tid < 4) {
            float a = cb;
            const float* cc = condb + tid * 80;
#pragma unroll 8
            for (int k = 0; k < 80; k++) a = fmaf(cgw[k], cc[k], a);
            float g = 0.2f + 0.8f * sigf(a);
            g = fminf(fmaxf(g, 0.001f), 20.0f);
            g_gain[(t * 4 + tid) * BATCH + b] = g;
        }
    }
}

// ================= cluster-split scan =================
// matvec_cl: rank computes output cols [rank*OUT/2, (rank+1)*OUT/2).
// Results written to local y AND peer's y via DSMEM. Caller must CLUSTER_SYNC
// before consumers read y. ACT: 0 none, 1 tanh.
template <int IN, int OUT, int ACT>
__device__ __forceinline__ void matvec_cl(const float* __restrict__ Wt,
                                          const float* __restrict__ x0, const float* __restrict__ x1,
                                          float* __restrict__ y0, float* __restrict__ y1,
                                          float* __restrict__ red,
                                          int rank, uint32_t prank) {
    constexpr int H2 = OUT / 2;
    constexpr int RG = H2 / 4;
    constexpr int S0 = NT / RG;
    constexpr int S = (S0 > 32) ? 32 : S0;
    int tid = threadIdx.x;
    int sl = tid / RG;
    int rg = tid - sl * RG;
    const float* Wb = Wt + rank * H2;
    if (sl < S) {
        float4 a0 = make_float4(0.f, 0.f, 0.f, 0.f);
        float4 a1 = make_float4(0.f, 0.f, 0.f, 0.f);
#pragma unroll 16
        for (int k = sl; k < IN; k += S) {
            float xk0 = x0[k], xk1 = x1[k];
            float4 w = __ldg(reinterpret_cast<const float4*>(Wb + k * OUT) + rg);
            a0.x = fmaf(w.x, xk0, a0.x); a0.y = fmaf(w.y, xk0, a0.y);
            a0.z = fmaf(w.z, xk0, a0.z); a0.w = fmaf(w.w, xk0, a0.w);
            a1.x = fmaf(w.x, xk1, a1.x); a1.y = fmaf(w.y, xk1, a1.y);
            a1.z = fmaf(w.z, xk1, a1.z); a1.w = fmaf(w.w, xk1, a1.w);
        }
        float4* r0 = reinterpret_cast<float4*>(red + sl * H2) + rg;
        float4* r1 = reinterpret_cast<float4*>(red + 2048 + sl * H2) + rg;
        *r0 = a0; *r1 = a1;
    }
    __syncthreads();
    for (int o = tid; o < 2 * H2; o += NT) {
        int bb = o / H2, j = o - bb * H2;
        const float* r = red + bb * 2048;
        float t = 0.0f;
#pragma unroll
        for (int ss = 0; ss < S; ss++) t += r[ss * H2 + j];
        if (ACT == 1) t = tanhf(t);
        int jj = rank * H2 + j;
        float* y = bb ? y1 : y0;
        y[jj] = t;
        st_peer(su32(&y[jj]), t, prank);
    }
    __syncthreads();
}

// full local matvec (small OUT, no split/exchange) — for gout
template <int IN, int OUT, int ACT>
__device__ __forceinline__ void matvec_full(const float* __restrict__ Wt,
                                            const float* __restrict__ x0, const float* __restrict__ x1,
                                            float* __restrict__ y0, float* __restrict__ y1,
                                            float* __restrict__ red) {
    constexpr int RG = OUT / 4;
    constexpr int S0 = NT / RG;
    constexpr int S = (S0 > 32) ? 32 : S0;
    int tid = threadIdx.x;
    int sl = tid / RG;
    int rg = tid - sl * RG;
    if (sl < S) {
        float4 a0 = make_float4(0.f, 0.f, 0.f, 0.f);
        float4 a1 = make_float4(0.f, 0.f, 0.f, 0.f);
        const float4* __restrict__ W4 = reinterpret_cast<const float4*>(Wt) + rg;
#pragma unroll 16
        for (int k = sl; k < IN; k += S) {
            float xk0 = x0[k], xk1 = x1[k];
            float4 w = __ldg(&W4[k * RG]);
            a0.x = fmaf(w.x, xk0, a0.x); a0.y = fmaf(w.y, xk0, a0.y);
            a0.z = fmaf(w.z, xk0, a0.z); a0.w = fmaf(w.w, xk0, a0.w);
            a1.x = fmaf(w.x, xk1, a1.x); a1.y = fmaf(w.y, xk1, a1.y);
            a1.z = fmaf(w.z, xk1, a1.z); a1.w = fmaf(w.w, xk1, a1.w);
        }
        float4* r0 = reinterpret_cast<float4*>(red + sl * OUT) + rg;
        float4* r1 = reinterpret_cast<float4*>(red + 2048 + sl * OUT) + rg;
        *r0 = a0; *r1 = a1;
    }
    __syncthreads();
    for (int o = tid; o < 2 * OUT; o += NT) {
        int bb = o / OUT, j = o - bb * OUT;
        const float* r = red + bb * 2048;
        float t = 0.0f;
#pragma unroll
        for (int ss = 0; ss < S; ss++) t += r[ss * OUT + j];
        if (ACT == 1) t = tanhf(t);
        float* y = bb ? y1 : y0;
        y[j] = t;
    }
    __syncthreads();
}

__global__ __launch_bounds__(NT) __cluster_dims__(2, 1, 1)
void k_scan(const int* __restrict__ period,
            const float* __restrict__ gout_b,
            float* __restrict__ out) {
    int pair = blockIdx.x >> 1;
    int b0 = pair * 2;
    uint32_t rank;
    asm("mov.u32 %0, %%cluster_ctarank;" : "=r"(rank));
    uint32_t prank = rank ^ 1u;

    __shared__ __align__(16) float exc[2][256];
    __shared__ __align__(16) float xcat[2][328];   // [0:164) state, [164:328) tmp
    __shared__ __align__(16) float s1[2][160], s2[2][128], s3[2][128];
    __shared__ __align__(16) float buf_t[2][192];  // tanh pre-glu buffer (fwc / skip)
    __shared__ __align__(16) float fwc_out[2][192];
    __shared__ __align__(16) float gi[2][480], gh[2][480];
    __shared__ __align__(16) float g1b[2][160], g2b[2][128], g3b[2][128];
    __shared__ __align__(16) float skin[2][688];   // GRU inputs + skip_in
    __shared__ __align__(16) float skipv[2][128];
    __shared__ __align__(16) float pgb[2][4];
    __shared__ __align__(16) float red[4096];
    __shared__ float sgain[2];
    __shared__ int   sper[2];
    int tid = threadIdx.x;

    for (int i = tid; i < 2 * 256; i += NT) ((float*)exc)[i] = 0.0f;
    for (int i = tid; i < 2 * 328; i += NT) ((float*)xcat)[i] = 0.0f;
    for (int i = tid; i < 2 * 160; i += NT) ((float*)s1)[i] = 0.0f;
    for (int i = tid; i < 2 * 128; i += NT) ((float*)s2)[i] = 0.0f;
    for (int i = tid; i < 2 * 128; i += NT) ((float*)s3)[i] = 0.0f;
    __syncthreads();
    CLUSTER_SYNC();

    int base = 0;  // exc circular base
    for (int s = 0; s < NSTEP; s++) {
        int frame = s >> 2, sub = s & 3;
        // P0a: scalars + state shift (redundant in both CTAs)
        if (tid < 4) {
            int bb = tid >> 1;
            if (tid & 1) {
                int p = period[(b0 + bb) * TT + 3 + frame];
                sper[bb] = min(max(p, 32), 254);
            } else {
                sgain[bb] = g_gain[s * BATCH + b0 + bb];
            }
        }
        if (tid < 328) {
            int bb = tid >= 164;
            int j = bb ? tid - 164 : tid;
            xcat[bb][j] = xcat[bb][164 + j];
        }
        __syncthreads();
        if (tid < 328) {
            int bb = tid >= 164;
            int j = bb ? tid - 164 : tid;
            float invg = 1.0f / (1e-5f + sgain[bb]);
            float v;
            if (j < 80) {
                v = g_cond[((size_t)((b0 + bb) * TC + frame)) * 320 + sub * 80 + j];
            } else if (j < 124) {
                int i2 = j - 80;
                int idx = 254 - sper[bb] + i2;
                if (idx >= 256) idx -= sper[bb];
                idx = max(0, min(255, idx));
                v = exc[bb][(base + idx) & 255] * invg;
            } else {
                v = exc[bb][(base + 216 + (j - 124)) & 255] * invg;
            }
            xcat[bb][164 + j] = v;
        }
        __syncthreads();

        // fwc (split) -> bt
        matvec_cl<328, 192, 1>(g_wt + OFF_FWC, xcat[0], xcat[1], buf_t[0], buf_t[1], red, rank, prank);
        CLUSTER_SYNC();
        // fwcg (split) -> gh
        matvec_cl<192, 192, 0>(g_wt + OFF_FWCG, buf_t[0], buf_t[1], gh[0], gh[1], red, rank, prank);
        CLUSTER_SYNC();
        for (int i = tid; i < 2 * 192; i += NT) {
            int bb = i / 192, j = i - bb * 192;
            fwc_out[bb][j] = buf_t[bb][j] * sigf(gh[bb][j]);
        }
        __syncthreads();

        // gout: tiny, full-local in both CTAs
        matvec_full<192, 4, 0>(g_wt + OFF_GOUT, fwc_out[0], fwc_out[1], pgb[0], pgb[1], red);
        if (tid < 8) {
            int bb = tid >> 2, j = tid & 3;
            pgb[bb][j] = sigf(pgb[bb][j] + gout_b[j]);
        }
        __syncthreads();

        // GRU1 input (272)
        for (int i = tid; i < 2 * 272; i += NT) {
            int bb = i / 272, j = i - bb * 272;
            float v;
            if (j < 192) v = fwc_out[bb][j];
            else if (j < 232) v = pgb[bb][0] * xcat[bb][164 + 82 + (j - 192)];
            else v = xcat[bb][164 + 124 + (j - 232)];
            skin[bb][j] = v;
        }
        __syncthreads();
        matvec_cl<272, 480, 0>(g_wt + OFF_G1IH, skin[0], skin[1], gi[0], gi[1], red, rank, prank);
        matvec_cl<160, 480, 0>(g_wt + OFF_G1HH, s1[0], s1[1], gh[0], gh[1], red, rank, prank);
        CLUSTER_SYNC();
        for (int i = tid; i < 2 * 160; i += NT) {
            int bb = i / 160, o = i - bb * 160;
            float r = sigf(gi[bb][o] + gh[bb][o]);
            float z = sigf(gi[bb][160 + o] + gh[bb][160 + o]);
            float n = tanhf(gi[bb][320 + o] + r * gh[bb][320 + o]);
            s1[bb][o] = (1.0f - z) * n + z * s1[bb][o];
        }
        __syncthreads();
        matvec_cl<160, 160, 0>(g_wt + OFF_GLU1, s1[0], s1[1], gh[0], gh[1], red, rank, prank);
        CLUSTER_SYNC();
        for (int i = tid; i < 2 * 160; i += NT) {
            int bb = i / 160, o = i - bb * 160;
            g1b[bb][o] = s1[bb][o] * sigf(gh[bb][o]);
        }
        __syncthreads();

        // GRU2 input (240)
        for (int i = tid; i < 2 * 240; i += NT) {
            int bb = i / 240, j = i - bb * 240;
            float v;
            if (j < 160) v = g1b[bb][j];
            else if (j < 200) v = pgb[bb][1] * xcat[bb][164 + 82 + (j - 160)];
            else v = xcat[bb][164 + 124 + (j - 200)];
            skin[bb][j] = v;
        }
        __syncthreads();
        matvec_cl<240, 384, 0>(g_wt + OFF_G2IH, skin[0], skin[1], gi[0], gi[1], red, rank, prank);
        matvec_cl<128, 384, 0>(g_wt + OFF_G2HH, s2[0], s2[1], gh[0], gh[1], red, rank, prank);
        CLUSTER_SYNC();
        for (int i = tid; i < 2 * 128; i += NT) {
            int bb = i / 128, o = i - bb * 128;
            float r = sigf(gi[bb][o] + gh[bb][o]);
            float z = sigf(gi[bb][128 + o] + gh[bb][128 + o]);
            float n = tanhf(gi[bb][256 + o] + r * gh[bb][256 + o]);
            s2[bb][o] = (1.0f - z) * n + z * s2[bb][o];
        }
        __syncthreads();
        matvec_cl<128, 128, 0>(g_wt + OFF_GLU2, s2[0], s2[1], gh[0], gh[1], red, rank, prank);
        CLUSTER_SYNC();
        for (int i = tid; i < 2 * 128; i += NT) {
            int bb = i / 128, o = i - bb * 128;
            g2b[bb][o] = s2[bb][o] * sigf(gh[bb][o]);
        }
        __syncthreads();

        // GRU3 input (208)
        for (int i = tid; i < 2 * 208; i += NT) {
            int bb = i / 208, j = i - bb * 208;
            float v;
            if (j < 128) v = g2b[bb][j];
            else if (j < 168) v = pgb[bb][2] * xcat[bb][164 + 82 + (j - 128)];
            else v = xcat[bb][164 + 124 + (j - 168)];
            skin[bb][j] = v;
        }
        __syncthreads();
        matvec_cl<208, 384, 0>(g_wt + OFF_G3IH, skin[0], skin[1], gi[0], gi[1], red, rank, prank);
        matvec_cl<128, 384, 0>(g_wt + OFF_G3HH, s3[0], s3[1], gh[0], gh[1], red, rank, prank);
        CLUSTER_SYNC();
        for (int i = tid; i < 2 * 128; i += NT) {
            int bb = i / 128, o = i - bb * 128;
            float r = sigf(gi[bb][o] + gh[bb][o]);
            float z = sigf(gi[bb][128 + o] + gh[bb][128 + o]);
            float n = tanhf(gi[bb][256 + o] + r * gh[bb][256 + o]);
            s3[bb][o] = (1.0f - z) * n + z * s3[bb][o];
        }
        __syncthreads();
        matvec_cl<128, 128, 0>(g_wt + OFF_GLU3, s3[0], s3[1], gh[0], gh[1], red, rank, prank);
        CLUSTER_SYNC();
        for (int i = tid; i < 2 * 128; i += NT) {
            int bb = i / 128, o = i - bb * 128;
            g3b[bb][o] = s3[bb][o] * sigf(gh[bb][o]);
        }
        __syncthreads();

        // skip_in (688)
        for (int i = tid; i < 2 * 688; i += NT) {
            int bb = i / 688, j = i - bb * 688;
            float v;
            if (j < 160) v = g1b[bb][j];
            else if (j < 288) v = g2b[bb][j - 160];
            else if (j < 416) v = g3b[bb][j - 288];
            else if (j < 608) v = fwc_out[bb][j - 416];
            else if (j < 648) v = pgb[bb][3] * xcat[bb][164 + 82 + (j - 608)];
            else v = xcat[bb][164 + 124 + (j - 648)];
            skin[bb][j] = v;
        }
        __syncthreads();
        matvec_cl<688, 128, 1>(g_wt + OFF_SKIP, skin[0], skin[1], buf_t[0], buf_t[1], red, rank, prank);
        CLUSTER_SYNC();
        matvec_cl<128, 128, 0>(g_wt + OFF_SKIPG, buf_t[0], buf_t[1], gh[0], gh[1], red, rank, prank);
        CLUSTER_SYNC();
        for (int i = tid; i < 2 * 128; i += NT) {
            int bb = i / 128, j = i - bb * 128;
            skipv[bb][j] = buf_t[bb][j] * sigf(gh[bb][j]);
        }
        __syncthreads();

        // sig (split) -> gi
        matvec_cl<128, 40, 1>(g_wt + OFF_SIG, skipv[0], skipv[1], gi[0], gi[1], red, rank, prank);
        CLUSTER_SYNC();
        for (int i = tid; i < 2 * 40; i += NT) {
            int bb = i / 40, j = i - bb * 40;
            float v = gi[bb][j] * sgain[bb];
            exc[bb][(base + j) & 255] = v;   // becomes logical [216+j] after base shift
            if (rank == 0)
                out[(size_t)(b0 + bb) * 80000 + s * 40 + j] = v;
        }
        __syncthreads();
        base = (base + 40) & 255;
    }
    CLUSTER_SYNC();
}

// ---------------- launch ----------------
extern "C" void kernel_launch(void* const* d_in, const int* in_sizes, int n_in,
                              void* d_out, int out_size) {
    const float* features = (const float*)d_in[0];
    const int*   period   = (const int*)d_in[1];
    const float* pembed   = (const float*)d_in[2];
    const float* fd1_w    = (const float*)d_in[3];
    const float* fconv1_w = (const float*)d_in[4];
    const float* fd2_w    = (const float*)d_in[5];
    const float* cg_w     = (const float*)d_in[6];
    const float* cg_b     = (const float*)d_in[7];
    const float* gout_b   = (const float*)d_in[23];
    float* out = (float*)d_out;

    WP wp;
    for (int i = 0; i < 15; i++) wp.p[i] = (const float*)d_in[8 + i];

    cudaFuncSetAttribute(k_convn, cudaFuncAttributeMaxDynamicSharedMemorySize, CONV_SMEM);
    cudaFuncSetAttribute(k_fd2n, cudaFuncAttributeMaxDynamicSharedMemorySize, FD2_SMEM);

    dim3 tg((130560 + 255) / 256, 15);   // max layer elems = 480*272
    k_transpose_all<<<tg, 256>>>(wp);
    k_fd1n<<<BATCH, 256>>>(features, period, pembed, fd1_w);
    k_convn<<<dim3(BATCH, 2), 128, CONV_SMEM>>>(fconv1_w);
    k_fd2n<<<BATCH, 320, FD2_SMEM>>>(fd2_w, cg_w, cg_b);
    k_scan<<<BATCH, NT>>>(period, gout_b, out);   // grid=128, cluster(2,1,1)
    (void)in_sizes; (void)n_in; (void)out_size;
}

// round 15
// speedup vs baseline: 1.4397x; 1.4397x over previous
#include <cuda_runtime.h>
#include <cuda_fp16.h>
#include <math.h>
#include <stdint.h>

#define BATCH   128
#define TT      504
#define TF      502      // tokens after features[:,2:]
#define TC      500      // cond frames
#define NSTEP   2000
#define NT      512      // threads in scan CTA

// ---------------- transposed-weight offsets (elements) ----------------
#define OFF_FWC    0          // (192,328)
#define OFF_FWCG   62976      // (192,192)
#define OFF_G1IH   99840      // (480,272)
#define OFF_G1HH   230400     // (480,160)
#define OFF_GLU1   307200     // (160,160)
#define OFF_G2IH   332800     // (384,240)
#define OFF_G2HH   424960     // (384,128)
#define OFF_GLU2   474112     // (128,128)
#define OFF_G3IH   490496     // (384,208)
#define OFF_G3HH   570368     // (384,128)
#define OFF_GLU3   619520     // (128,128)
#define OFF_SKIP   635904     // (128,688)
#define OFF_SKIPG  723968     // (128,128)
#define OFF_SIG    740352     // (40,128)
#define OFF_GOUT   745472     // (4,192)
#define WT_TOTAL   746240

// ---------------- device scratch ----------------
__device__ float  g_x[BATCH * TF * 64];        // fd1 output
__device__ float  g_y[BATCH * TC * 128];       // conv output
__device__ float  g_cond[BATCH * TC * 320];    // fd2 output
__device__ float  g_gain[NSTEP * BATCH];       // precomputed gains
__device__ float  g_wt[WT_TOTAL];              // fp32 transposed weights (gout path)
__device__ __half g_wth[WT_TOTAL];             // fp16 transposed weights [in][out]

__device__ __forceinline__ float sigf(float x) { return 1.0f / (1.0f + expf(-x)); }

// ---------------- fused weight transpose: Wt[k*out+o] = W[o*in+k] ----------------
struct WP { const float* p[15]; };
__constant__ int T_OFF[15] = {OFF_FWC, OFF_FWCG, OFF_G1IH, OFF_G1HH, OFF_GLU1,
                              OFF_G2IH, OFF_G2HH, OFF_GLU2, OFF_G3IH, OFF_G3HH,
                              OFF_GLU3, OFF_SKIP, OFF_SKIPG, OFF_SIG, OFF_GOUT};
__constant__ int T_OUT[15] = {192, 192, 480, 480, 160, 384, 384, 128, 384, 384, 128, 128, 128, 40, 4};
__constant__ int T_IN [15] = {328, 192, 272, 160, 160, 240, 128, 128, 208, 128, 128, 688, 128, 128, 192};

__global__ void k_transpose_all(WP wp) {
    int l = blockIdx.y;
    int i = blockIdx.x * blockDim.x + threadIdx.x;
    int out = T_OUT[l], in = T_IN[l];
    if (i < out * in) {
        int o = i / in, k = i - o * in;
        float w = wp.p[l][i];
        g_wt[T_OFF[l] + k * out + o] = w;
        g_wth[T_OFF[l] + k * out + o] = __float2half(w);
    }
}

// ---------------- fd1: weight-stationary, 1 block per batch elem ----------------
__global__ void k_fd1n(const float* __restrict__ feat, const int* __restrict__ period,
                       const float* __restrict__ pembed, const float* __restrict__ fd1) {
    int b = blockIdx.x;
    __shared__ float wd1[64 * 33];   // padded stride 33 -> conflict-free
    int tid = threadIdx.x;           // 256
    for (int i = tid; i < 64 * 32; i += 256) {
        int o = i >> 5, k = i & 31;
        wd1[o * 33 + k] = fd1[i];
    }
    __syncthreads();
    int warp = tid >> 5, lane = tid & 31;
    for (int t = warp; t < TF; t += 8) {
        int per = period[b * TT + t + 2];
        per = min(max(per, 32), 254);
        float v;
        if (lane < 20) v = feat[(b * TT + t + 2) * 20 + lane];
        else           v = pembed[(per - 32) * 12 + (lane - 20)];
        float a0 = 0.0f, a1 = 0.0f;
#pragma unroll
        for (int k = 0; k < 32; k++) {
            float xk = __shfl_sync(0xffffffffu, v, k);
            a0 = fmaf(wd1[lane * 33 + k], xk, a0);
            a1 = fmaf(wd1[(lane + 32) * 33 + k], xk, a1);
        }
        g_x[(b * TF + t) * 64 + lane] = tanhf(a0);
        g_x[(b * TF + t) * 64 + lane + 32] = tanhf(a1);
    }
}

// ---------------- conv1d: weight-stationary, 2 blocks per batch elem ----------------
#define CONV_SMEM ((128 * 193 + 192) * 4)
__global__ void k_convn(const float* __restrict__ wconv) {
    int b = blockIdx.x;
    int t0 = blockIdx.y * 250;
    extern __shared__ float smc[];
    float* wc = smc;                 // 128 x 193 (padded)
    float* xin = smc + 128 * 193;    // 192
    int tid = threadIdx.x;           // 128
    for (int i = tid; i < 128 * 192; i += 128) {
        int oc = i / 192, k = i - oc * 192;
        wc[oc * 193 + k] = wconv[i];
    }
    __syncthreads();
    for (int t = t0; t < t0 + 250; t++) {
        for (int i = tid; i < 192; i += 128)
            xin[i] = g_x[(b * TF + t + (i >> 6)) * 64 + (i & 63)];
        __syncthreads();
        float acc = 0.0f;
        const float* w = wc + tid * 193;
#pragma unroll 8
        for (int ic = 0; ic < 64; ic++) {
            acc = fmaf(w[ic * 3 + 0], xin[ic], acc);
            acc = fmaf(w[ic * 3 + 1], xin[64 + ic], acc);
            acc = fmaf(w[ic * 3 + 2], xin[128 + ic], acc);
        }
        g_y[(b * TC + t) * 128 + tid] = tanhf(acc);
        __syncthreads();
    }
}

// ---------------- fd2 + gains: weight-stationary, 1 block per batch elem ----------------
#define FD2_SMEM ((320 * 129 + 128 + 320 + 80) * 4)
__global__ void k_fd2n(const float* __restrict__ fd2, const float* __restrict__ cg_w,
                       const float* __restrict__ cg_b) {
    int b = blockIdx.x;
    extern __shared__ float smf[];
    float* wf = smf;                       // 320 x 129 (padded)
    float* ybuf = wf + 320 * 129;          // 128
    float* condb = ybuf + 128;             // 320
    float* cgw = condb + 320;              // 80
    int tid = threadIdx.x;                 // 320
    for (int i = tid; i < 320 * 128; i += 320) {
        int o = i >> 7, k = i & 127;
        wf[o * 129 + k] = fd2[i];
    }
    if (tid < 80) cgw[tid] = cg_w[tid];
    __syncthreads();
    float cb = cg_b[0];
    for (int t = 0; t < TC; t++) {
        if (tid < 128) ybuf[tid] = g_y[(b * TC + t) * 128 + tid];
        __syncthreads();
        float acc = 0.0f;
        const float* w = wf + tid * 129;
#pragma unroll 8
        for (int k = 0; k < 128; k++) acc = fmaf(w[k], ybuf[k], acc);
        float cv = tanhf(acc);
        condb[tid] = cv;
        g_cond[((size_t)(b * TC + t)) * 320 + tid] = cv;
        __syncthreads();
        if (tid < 4) {
            float a = cb;
            const float* cc = condb + tid * 80;
#pragma unroll 8
            for (int k = 0; k < 80; k++) a = fmaf(cgw[k], cc[k], a);
            float g = 0.2f + 0.8f * sigf(a);
            g = fminf(fmaxf(g, 0.001f), 20.0f);
            g_gain[(t * 4 + tid) * BATCH + b] = g;
        }
    }
}

// ================= scan =================
// fp16-weight matvec: each LDG.128 carries 8 outputs at one k (fp32 accum).
// red is dynamic smem: 8192 floats (4096 per batch).
template <int IN, int OUT, int ACT>
__device__ __forceinline__ void matvec_h(const __half* __restrict__ Wt,
                                         const float* __restrict__ x0, const float* __restrict__ x1,
                                         float* __restrict__ y0, float* __restrict__ y1,
                                         float* __restrict__ red) {
    constexpr int RG = OUT / 8;                      // 8-output groups
    constexpr int S0 = NT / RG;
    constexpr int S = (S0 > 32) ? 32 : S0;           // k-slices
    static_assert(S * OUT <= 4096, "red overflow");
    int tid = threadIdx.x;
    int sl = tid / RG;
    int rg = tid - sl * RG;
    if (sl < S) {
        float a0[8], a1[8];
#pragma unroll
        for (int i = 0; i < 8; i++) { a0[i] = 0.0f; a1[i] = 0.0f; }
        const uint4* __restrict__ W4 = reinterpret_cast<const uint4*>(Wt) + rg;
#pragma unroll 8
        for (int k = sl; k < IN; k += S) {
            uint4 wv = __ldg(&W4[k * RG]);
            float xk0 = x0[k], xk1 = x1[k];
            const __half2* hp = reinterpret_cast<const __half2*>(&wv);
#pragma unroll
            for (int i = 0; i < 4; i++) {
                float2 w = __half22float2(hp[i]);
                a0[2 * i]     = fmaf(w.x, xk0, a0[2 * i]);
                a0[2 * i + 1] = fmaf(w.y, xk0, a0[2 * i + 1]);
                a1[2 * i]     = fmaf(w.x, xk1, a1[2 * i]);
                a1[2 * i + 1] = fmaf(w.y, xk1, a1[2 * i + 1]);
            }
        }
        float4* r0 = reinterpret_cast<float4*>(red + sl * OUT + rg * 8);
        float4* r1 = reinterpret_cast<float4*>(red + 4096 + sl * OUT + rg * 8);
        r0[0] = make_float4(a0[0], a0[1], a0[2], a0[3]);
        r0[1] = make_float4(a0[4], a0[5], a0[6], a0[7]);
        r1[0] = make_float4(a1[0], a1[1], a1[2], a1[3]);
        r1[1] = make_float4(a1[4], a1[5], a1[6], a1[7]);
    }
    __syncthreads();
    for (int o = tid; o < 2 * OUT; o += NT) {
        int bb = o / OUT, j = o - bb * OUT;
        const float* r = red + bb * 4096;
        float t = 0.0f;
#pragma unroll
        for (int ss = 0; ss < S; ss++) t += r[ss * OUT + j];
        if (ACT == 1) t = tanhf(t);
        float* y = bb ? y1 : y0;
        y[j] = t;
    }
    __syncthreads();
}

// fp32 matvec (gout only; OUT=4 not divisible by 8)
template <int IN, int OUT, int ACT>
__device__ __forceinline__ void matvec_f(const float* __restrict__ Wt,
                                         const float* __restrict__ x0, const float* __restrict__ x1,
                                         float* __restrict__ y0, float* __restrict__ y1,
                                         float* __restrict__ red) {
    constexpr int RG = OUT / 4;
    constexpr int S0 = NT / RG;
    constexpr int S = (S0 > 32) ? 32 : S0;
    int tid = threadIdx.x;
    int sl = tid / RG;
    int rg = tid - sl * RG;
    if (sl < S) {
        float4 a0 = make_float4(0.f, 0.f, 0.f, 0.f);
        float4 a1 = make_float4(0.f, 0.f, 0.f, 0.f);
        const float4* __restrict__ W4 = reinterpret_cast<const float4*>(Wt) + rg;
#pragma unroll 16
        for (int k = sl; k < IN; k += S) {
            float xk0 = x0[k], xk1 = x1[k];
            float4 w = __ldg(&W4[k * RG]);
            a0.x = fmaf(w.x, xk0, a0.x); a0.y = fmaf(w.y, xk0, a0.y);
            a0.z = fmaf(w.z, xk0, a0.z); a0.w = fmaf(w.w, xk0, a0.w);
            a1.x = fmaf(w.x, xk1, a1.x); a1.y = fmaf(w.y, xk1, a1.y);
            a1.z = fmaf(w.z, xk1, a1.z); a1.w = fmaf(w.w, xk1, a1.w);
        }
        float4* r0 = reinterpret_cast<float4*>(red + sl * OUT) + rg;
        float4* r1 = reinterpret_cast<float4*>(red + 4096 + sl * OUT) + rg;
        *r0 = a0; *r1 = a1;
    }
    __syncthreads();
    for (int o = tid; o < 2 * OUT; o += NT) {
        int bb = o / OUT, j = o - bb * OUT;
        const float* r = red + bb * 4096;
        float t = 0.0f;
#pragma unroll
        for (int ss = 0; ss < S; ss++) t += r[ss * OUT + j];
        if (ACT == 1) t = tanhf(t);
        float* y = bb ? y1 : y0;
        y[j] = t;
    }
    __syncthreads();
}

template <int H, int IN>
__device__ __forceinline__ void gru_glu(const __half* Wih, const __half* Whh, const __half* Wglu,
                                        const float* x0, const float* x1,
                                        float* h0, float* h1, float* g0, float* g1,
                                        float* gi0, float* gi1, float* gh0, float* gh1,
                                        float* red) {
    matvec_h<IN, 3 * H, 0>(Wih, x0, x1, gi0, gi1, red);
    matvec_h<H, 3 * H, 0>(Whh, h0, h1, gh0, gh1, red);
    int tid = threadIdx.x;
    for (int i = tid; i < 2 * H; i += NT) {
        int bb = i / H, o = i - bb * H;
        const float* gi = bb ? gi1 : gi0;
        const float* gh = bb ? gh1 : gh0;
        float* h = bb ? h1 : h0;
        float r = sigf(gi[o] + gh[o]);
        float z = sigf(gi[H + o] + gh[H + o]);
        float n = tanhf(gi[2 * H + o] + r * gh[2 * H + o]);
        h[o] = (1.0f - z) * n + z * h[o];
    }
    __syncthreads();
    matvec_h<H, H, 0>(Wglu, h0, h1, gh0, gh1, red);
    for (int i = tid; i < 2 * H; i += NT) {
        int bb = i / H, o = i - bb * H;
        const float* h = bb ? h1 : h0;
        const float* u = bb ? gh1 : gh0;
        float* g = bb ? g1 : g0;
        g[o] = h[o] * sigf(u[o]);
    }
    __syncthreads();
}

#define SCAN_DSMEM (8192 * 4)

__global__ __launch_bounds__(NT) void k_scan(const int* __restrict__ period,
                                             const float* __restrict__ gout_b,
                                             float* __restrict__ out) {
    int b0 = blockIdx.x * 2;
    extern __shared__ float red[];                 // 8192 floats
    __shared__ __align__(16) float exc[2][256];
    __shared__ __align__(16) float xcat[2][328];   // [0:164) state, [164:328) tmp
    __shared__ __align__(16) float s1[2][160], s2[2][128], s3[2][128];
    __shared__ __align__(16) float buf_t[2][192];  // tanh pre-glu buffer (fwc / skip)
    __shared__ __align__(16) float fwc_out[2][192];
    __shared__ __align__(16) float gi[2][480], gh[2][480];
    __shared__ __align__(16) float g1b[2][160], g2b[2][128], g3b[2][128];
    __shared__ __align__(16) float skin[2][688];   // GRU inputs + skip_in
    __shared__ __align__(16) float skipv[2][128];
    __shared__ __align__(16) float pgb[2][4];
    __shared__ float sgain[2];
    __shared__ int   sper[2];
    int tid = threadIdx.x;
    const __half* gwh = g_wth;

    for (int i = tid; i < 2 * 256; i += NT) ((float*)exc)[i] = 0.0f;
    for (int i = tid; i < 2 * 328; i += NT) ((float*)xcat)[i] = 0.0f;
    for (int i = tid; i < 2 * 160; i += NT) ((float*)s1)[i] = 0.0f;
    for (int i = tid; i < 2 * 128; i += NT) ((float*)s2)[i] = 0.0f;
    for (int i = tid; i < 2 * 128; i += NT) ((float*)s3)[i] = 0.0f;
    __syncthreads();

    int base = 0;  // exc circular base
    for (int s = 0; s < NSTEP; s++) {
        int frame = s >> 2, sub = s & 3;
        if (tid < 4) {
            int bb = tid >> 1;
            if (tid & 1) {
                int p = period[(b0 + bb) * TT + 3 + frame];
                sper[bb] = min(max(p, 32), 254);
            } else {
                sgain[bb] = g_gain[s * BATCH + b0 + bb];
            }
        }
        if (tid < 328) {
            int bb = tid >= 164;
            int j = bb ? tid - 164 : tid;
            xcat[bb][j] = xcat[bb][164 + j];
        }
        __syncthreads();
        if (tid < 328) {
            int bb = tid >= 164;
            int j = bb ? tid - 164 : tid;
            float invg = 1.0f / (1e-5f + sgain[bb]);
            float v;
            if (j < 80) {
                v = g_cond[((size_t)((b0 + bb) * TC + frame)) * 320 + sub * 80 + j];
            } else if (j < 124) {
                int i2 = j - 80;
                int idx = 254 - sper[bb] + i2;
                if (idx >= 256) idx -= sper[bb];
                idx = max(0, min(255, idx));
                v = exc[bb][(base + idx) & 255] * invg;
            } else {
                v = exc[bb][(base + 216 + (j - 124)) & 255] * invg;
            }
            xcat[bb][164 + j] = v;
        }
        __syncthreads();

        matvec_h<328, 192, 1>(gwh + OFF_FWC, xcat[0], xcat[1], buf_t[0], buf_t[1], red);
        matvec_h<192, 192, 0>(gwh + OFF_FWCG, buf_t[0], buf_t[1], gh[0], gh[1], red);
        for (int i = tid; i < 2 * 192; i += NT) {
            int bb = i / 192, j = i - bb * 192;
            fwc_out[bb][j] = buf_t[bb][j] * sigf(gh[bb][j]);
        }
        __syncthreads();

        matvec_f<192, 4, 0>(g_wt + OFF_GOUT, fwc_out[0], fwc_out[1], pgb[0], pgb[1], red);
        if (tid < 8) {
            int bb = tid >> 2, j = tid & 3;
            pgb[bb][j] = sigf(pgb[bb][j] + gout_b[j]);
        }
        __syncthreads();

        for (int i = tid; i < 2 * 272; i += NT) {
            int bb = i / 272, j = i - bb * 272;
            float v;
            if (j < 192) v = fwc_out[bb][j];
            else if (j < 232) v = pgb[bb][0] * xcat[bb][164 + 82 + (j - 192)];
            else v = xcat[bb][164 + 124 + (j - 232)];
            skin[bb][j] = v;
        }
        __syncthreads();
        gru_glu<160, 272>(gwh + OFF_G1IH, gwh + OFF_G1HH, gwh + OFF_GLU1,
                          skin[0], skin[1], s1[0], s1[1], g1b[0], g1b[1],
                          gi[0], gi[1], gh[0], gh[1], red);

        for (int i = tid; i < 2 * 240; i += NT) {
            int bb = i / 240, j = i - bb * 240;
            float v;
            if (j < 160) v = g1b[bb][j];
            else if (j < 200) v = pgb[bb][1] * xcat[bb][164 + 82 + (j - 160)];
            else v = xcat[bb][164 + 124 + (j - 200)];
            skin[bb][j] = v;
        }
        __syncthreads();
        gru_glu<128, 240>(gwh + OFF_G2IH, gwh + OFF_G2HH, gwh + OFF_GLU2,
                          skin[0], skin[1], s2[0], s2[1], g2b[0], g2b[1],
                          gi[0], gi[1], gh[0], gh[1], red);

        for (int i = tid; i < 2 * 208; i += NT) {
            int bb = i / 208, j = i - bb * 208;
            float v;
            if (j < 128) v = g2b[bb][j];
            else if (j < 168) v = pgb[bb][2] * xcat[bb][164 + 82 + (j - 128)];
            else v = xcat[bb][164 + 124 + (j - 168)];
            skin[bb][j] = v;
        }
        __syncthreads();
        gru_glu<128, 208>(gwh + OFF_G3IH, gwh + OFF_G3HH, gwh + OFF_GLU3,
                          skin[0], skin[1], s3[0], s3[1], g3b[0], g3b[1],
                          gi[0], gi[1], gh[0], gh[1], red);

        for (int i = tid; i < 2 * 688; i += NT) {
            int bb = i / 688, j = i - bb * 688;
            float v;
            if (j < 160) v = g1b[bb][j];
            else if (j < 288) v = g2b[bb][j - 160];
            else if (j < 416) v = g3b[bb][j - 288];
            else if (j < 608) v = fwc_out[bb][j - 416];
            else if (j < 648) v = pgb[bb][3] * xcat[bb][164 + 82 + (j - 608)];
            else v = xcat[bb][164 + 124 + (j - 648)];
            skin[bb][j] = v;
        }
        __syncthreads();
        matvec_h<688, 128, 1>(gwh + OFF_SKIP, skin[0], skin[1], buf_t[0], buf_t[1], red);
        matvec_h<128, 128, 0>(gwh + OFF_SKIPG, buf_t[0], buf_t[1], gh[0], gh[1], red);
        for (int i = tid; i < 2 * 128; i += NT) {
            int bb = i / 128, j = i - bb * 128;
            skipv[bb][j] = buf_t[bb][j] * sigf(gh[bb][j]);
        }
        __syncthreads();

        matvec_h<128, 40, 1>(gwh + OFF_SIG, skipv[0], skipv[1], gi[0], gi[1], red);
        for (int i = tid; i < 2 * 40; i += NT) {
            int bb = i / 40, j = i - bb * 40;
            float v = gi[bb][j] * sgain[bb];
            exc[bb][(base + j) & 255] = v;   // becomes logical [216+j] after base shift
            out[(size_t)(b0 + bb) * 80000 + s * 40 + j] = v;
        }
        __syncthreads();
        base = (base + 40) & 255;
    }
}

// ---------------- launch ----------------
extern "C" void kernel_launch(void* const* d_in, const int* in_sizes, int n_in,
                              void* d_out, int out_size) {
    const float* features = (const float*)d_in[0];
    const int*   period   = (const int*)d_in[1];
    const float* pembed   = (const float*)d_in[2];
    const float* fd1_w    = (const float*)d_in[3];
    const float* fconv1_w = (const float*)d_in[4];
    const float* fd2_w    = (const float*)d_in[5];
    const float* cg_w     = (const float*)d_in[6];
    const float* cg_b     = (const float*)d_in[7];
    const float* gout_b   = (const float*)d_in[23];
    float* out = (float*)d_out;

    WP wp;
    for (int i = 0; i < 15; i++) wp.p[i] = (const float*)d_in[8 + i];

    cudaFuncSetAttribute(k_convn, cudaFuncAttributeMaxDynamicSharedMemorySize, CONV_SMEM);
    cudaFuncSetAttribute(k_fd2n, cudaFuncAttributeMaxDynamicSharedMemorySize, FD2_SMEM);
    cudaFuncSetAttribute(k_scan, cudaFuncAttributeMaxDynamicSharedMemorySize, SCAN_DSMEM);

    dim3 tg((130560 + 255) / 256, 15);   // max layer elems = 480*272
    k_transpose_all<<<tg, 256>>>(wp);
    k_fd1n<<<BATCH, 256>>>(features, period, pembed, fd1_w);
    k_convn<<<dim3(BATCH, 2), 128, CONV_SMEM>>>(fconv1_w);
    k_fd2n<<<BATCH, 320, FD2_SMEM>>>(fd2_w, cg_w, cg_b);
    k_scan<<<BATCH / 2, NT, SCAN_DSMEM>>>(period, gout_b, out);
    (void)in_sizes; (void)n_in; (void)out_size;
}

// round 16
// speedup vs baseline: 1.8358x; 1.2751x over previous
#include <cuda_runtime.h>
#include <cuda_fp16.h>
#include <math.h>
#include <stdint.h>

#define BATCH   128
#define TT      504
#define TF      502      // tokens after features[:,2:]
#define TC      500      // cond frames
#define NSTEP   2000
#define NT      512      // threads in scan CTA

// ---------------- transposed-weight offsets (elements) ----------------
#define OFF_FWC    0          // (192,328)
#define OFF_FWCG   62976      // (192,192)
#define OFF_G1IH   99840      // (480,272)
#define OFF_G1HH   230400     // (480,160)
#define OFF_GLU1   307200     // (160,160)
#define OFF_G2IH   332800     // (384,240)
#define OFF_G2HH   424960     // (384,128)
#define OFF_GLU2   474112     // (128,128)
#define OFF_G3IH   490496     // (384,208)
#define OFF_G3HH   570368     // (384,128)
#define OFF_GLU3   619520     // (128,128)
#define OFF_SKIP   635904     // (128,688)
#define OFF_SKIPG  723968     // (128,128)
#define OFF_SIG    740352     // (40,128)
#define OFF_GOUT   745472     // (4,192)
#define WT_TOTAL   746240

// ---------------- device scratch ----------------
__device__ float  g_x[BATCH * TF * 64];        // fd1 output
__device__ float  g_y[BATCH * TC * 128];       // conv output
__device__ float  g_cond[BATCH * TC * 320];    // fd2 output
__device__ float  g_gain[NSTEP * BATCH];       // precomputed gains
__device__ float  g_wt[WT_TOTAL];              // fp32 transposed weights (gout path)
__device__ __half g_wth[WT_TOTAL];             // fp16 transposed weights [in][out]

__device__ __forceinline__ float sigf(float x) { return 1.0f / (1.0f + expf(-x)); }

// ---------------- fused weight transpose: Wt[k*out+o] = W[o*in+k] ----------------
struct WP { const float* p[15]; };
__constant__ int T_OFF[15] = {OFF_FWC, OFF_FWCG, OFF_G1IH, OFF_G1HH, OFF_GLU1,
                              OFF_G2IH, OFF_G2HH, OFF_GLU2, OFF_G3IH, OFF_G3HH,
                              OFF_GLU3, OFF_SKIP, OFF_SKIPG, OFF_SIG, OFF_GOUT};
__constant__ int T_OUT[15] = {192, 192, 480, 480, 160, 384, 384, 128, 384, 384, 128, 128, 128, 40, 4};
__constant__ int T_IN [15] = {328, 192, 272, 160, 160, 240, 128, 128, 208, 128, 128, 688, 128, 128, 192};

__global__ void k_transpose_all(WP wp) {
    int l = blockIdx.y;
    int i = blockIdx.x * blockDim.x + threadIdx.x;
    int out = T_OUT[l], in = T_IN[l];
    if (i < out * in) {
        int o = i / in, k = i - o * in;
        float w = wp.p[l][i];
        g_wt[T_OFF[l] + k * out + o] = w;
        g_wth[T_OFF[l] + k * out + o] = __float2half(w);
    }
}

// ---------------- fd1: weight-stationary, 1 block per batch elem ----------------
__global__ void k_fd1n(const float* __restrict__ feat, const int* __restrict__ period,
                       const float* __restrict__ pembed, const float* __restrict__ fd1) {
    int b = blockIdx.x;
    __shared__ float wd1[64 * 33];   // padded stride 33 -> conflict-free
    int tid = threadIdx.x;           // 256
    for (int i = tid; i < 64 * 32; i += 256) {
        int o = i >> 5, k = i & 31;
        wd1[o * 33 + k] = fd1[i];
    }
    __syncthreads();
    int warp = tid >> 5, lane = tid & 31;
    for (int t = warp; t < TF; t += 8) {
        int per = period[b * TT + t + 2];
        per = min(max(per, 32), 254);
        float v;
        if (lane < 20) v = feat[(b * TT + t + 2) * 20 + lane];
        else           v = pembed[(per - 32) * 12 + (lane - 20)];
        float a0 = 0.0f, a1 = 0.0f;
#pragma unroll
        for (int k = 0; k < 32; k++) {
            float xk = __shfl_sync(0xffffffffu, v, k);
            a0 = fmaf(wd1[lane * 33 + k], xk, a0);
            a1 = fmaf(wd1[(lane + 32) * 33 + k], xk, a1);
        }
        g_x[(b * TF + t) * 64 + lane] = tanhf(a0);
        g_x[(b * TF + t) * 64 + lane + 32] = tanhf(a1);
    }
}

// ---------------- conv1d: weight-stationary, 2 blocks per batch elem ----------------
#define CONV_SMEM ((128 * 193 + 192) * 4)
__global__ void k_convn(const float* __restrict__ wconv) {
    int b = blockIdx.x;
    int t0 = blockIdx.y * 250;
    extern __shared__ float smc[];
    float* wc = smc;                 // 128 x 193 (padded)
    float* xin = smc + 128 * 193;    // 192
    int tid = threadIdx.x;           // 128
    for (int i = tid; i < 128 * 192; i += 128) {
        int oc = i / 192, k = i - oc * 192;
        wc[oc * 193 + k] = wconv[i];
    }
    __syncthreads();
    for (int t = t0; t < t0 + 250; t++) {
        for (int i = tid; i < 192; i += 128)
            xin[i] = g_x[(b * TF + t + (i >> 6)) * 64 + (i & 63)];
        __syncthreads();
        float acc = 0.0f;
        const float* w = wc + tid * 193;
#pragma unroll 8
        for (int ic = 0; ic < 64; ic++) {
            acc = fmaf(w[ic * 3 + 0], xin[ic], acc);
            acc = fmaf(w[ic * 3 + 1], xin[64 + ic], acc);
            acc = fmaf(w[ic * 3 + 2], xin[128 + ic], acc);
        }
        g_y[(b * TC + t) * 128 + tid] = tanhf(acc);
        __syncthreads();
    }
}

// ---------------- fd2 + gains: weight-stationary, 1 block per batch elem ----------------
#define FD2_SMEM ((320 * 129 + 128 + 320 + 80) * 4)
__global__ void k_fd2n(const float* __restrict__ fd2, const float* __restrict__ cg_w,
                       const float* __restrict__ cg_b) {
    int b = blockIdx.x;
    extern __shared__ float smf[];
    float* wf = smf;                       // 320 x 129 (padded)
    float* ybuf = wf + 320 * 129;          // 128
    float* condb = ybuf + 128;             // 320
    float* cgw = condb + 320;              // 80
    int tid = threadIdx.x;                 // 320
    for (int i = tid; i < 320 * 128; i += 320) {
        int o = i >> 7, k = i & 127;
        wf[o * 129 + k] = fd2[i];
    }
    if (tid < 80) cgw[tid] = cg_w[tid];
    __syncthreads();
    float cb = cg_b[0];
    for (int t = 0; t < TC; t++) {
        if (tid < 128) ybuf[tid] = g_y[(b * TC + t) * 128 + tid];
        __syncthreads();
        float acc = 0.0f;
        const float* w = wf + tid * 129;
#pragma unroll 8
        for (int k = 0; k < 128; k++) acc = fmaf(w[k], ybuf[k], acc);
        float cv = tanhf(acc);
        condb[tid] = cv;
        g_cond[((size_t)(b * TC + t)) * 320 + tid] = cv;
        __syncthreads();
        if (tid < 4) {
            float a = cb;
            const float* cc = condb + tid * 80;
#pragma unroll 8
            for (int k = 0; k < 80; k++) a = fmaf(cgw[k], cc[k], a);
            float g = 0.2f + 0.8f * sigf(a);
            g = fminf(fmaxf(g, 0.001f), 20.0f);
            g_gain[(t * 4 + tid) * BATCH + b] = g;
        }
    }
}

// ================= scan: BPC=1, fp16 weights =================
// fp16-weight matvec, single batch: each LDG.128 carries 8 outputs at one k.
// red: dynamic smem, 4096 floats.
template <int IN, int OUT, int ACT>
__device__ __forceinline__ void matvec_h(const __half* __restrict__ Wt,
                                         const float* __restrict__ x,
                                         float* __restrict__ y,
                                         float* __restrict__ red) {
    constexpr int RG = OUT / 8;                      // 8-output groups
    constexpr int S0 = NT / RG;
    constexpr int S = (S0 > 32) ? 32 : S0;           // k-slices
    static_assert(S * OUT <= 4096, "red overflow");
    int tid = threadIdx.x;
    int sl = tid / RG;
    int rg = tid - sl * RG;
    if (sl < S) {
        float a[8];
#pragma unroll
        for (int i = 0; i < 8; i++) a[i] = 0.0f;
        const uint4* __restrict__ W4 = reinterpret_cast<const uint4*>(Wt) + rg;
#pragma unroll 8
        for (int k = sl; k < IN; k += S) {
            uint4 wv = __ldg(&W4[k * RG]);
            float xk = x[k];
            const __half2* hp = reinterpret_cast<const __half2*>(&wv);
#pragma unroll
            for (int i = 0; i < 4; i++) {
                float2 w = __half22float2(hp[i]);
                a[2 * i]     = fmaf(w.x, xk, a[2 * i]);
                a[2 * i + 1] = fmaf(w.y, xk, a[2 * i + 1]);
            }
        }
        float4* r = reinterpret_cast<float4*>(red + sl * OUT + rg * 8);
        r[0] = make_float4(a[0], a[1], a[2], a[3]);
        r[1] = make_float4(a[4], a[5], a[6], a[7]);
    }
    __syncthreads();
    for (int o = tid; o < OUT; o += NT) {
        float t = 0.0f;
#pragma unroll
        for (int ss = 0; ss < S; ss++) t += red[ss * OUT + o];
        if (ACT == 1) t = tanhf(t);
        y[o] = t;
    }
    __syncthreads();
}

// fp32 matvec (gout only; OUT=4)
template <int IN, int OUT, int ACT>
__device__ __forceinline__ void matvec_f(const float* __restrict__ Wt,
                                         const float* __restrict__ x,
                                         float* __restrict__ y,
                                         float* __restrict__ red) {
    constexpr int RG = OUT / 4;
    constexpr int S0 = NT / RG;
    constexpr int S = (S0 > 32) ? 32 : S0;
    int tid = threadIdx.x;
    int sl = tid / RG;
    int rg = tid - sl * RG;
    if (sl < S) {
        float4 a = make_float4(0.f, 0.f, 0.f, 0.f);
        const float4* __restrict__ W4 = reinterpret_cast<const float4*>(Wt) + rg;
#pragma unroll 16
        for (int k = sl; k < IN; k += S) {
            float xk = x[k];
            float4 w = __ldg(&W4[k * RG]);
            a.x = fmaf(w.x, xk, a.x); a.y = fmaf(w.y, xk, a.y);
            a.z = fmaf(w.z, xk, a.z); a.w = fmaf(w.w, xk, a.w);
        }
        *(reinterpret_cast<float4*>(red + sl * OUT) + rg) = a;
    }
    __syncthreads();
    for (int o = tid; o < OUT; o += NT) {
        float t = 0.0f;
#pragma unroll
        for (int ss = 0; ss < S; ss++) t += red[ss * OUT + o];
        if (ACT == 1) t = tanhf(t);
        y[o] = t;
    }
    __syncthreads();
}

template <int H, int IN>
__device__ __forceinline__ void gru_glu(const __half* Wih, const __half* Whh, const __half* Wglu,
                                        const float* x, float* h, float* g,
                                        float* gi, float* gh, float* red) {
    matvec_h<IN, 3 * H, 0>(Wih, x, gi, red);
    matvec_h<H, 3 * H, 0>(Whh, h, gh, red);
    int tid = threadIdx.x;
    if (tid < H) {
        int o = tid;
        float r = sigf(gi[o] + gh[o]);
        float z = sigf(gi[H + o] + gh[H + o]);
        float n = tanhf(gi[2 * H + o] + r * gh[2 * H + o]);
        h[o] = (1.0f - z) * n + z * h[o];
    }
    __syncthreads();
    matvec_h<H, H, 0>(Wglu, h, gh, red);
    if (tid < H) {
        g[tid] = h[tid] * sigf(gh[tid]);
    }
    __syncthreads();
}

#define SCAN_DSMEM (4096 * 4)

__global__ __launch_bounds__(NT) void k_scan(const int* __restrict__ period,
                                             const float* __restrict__ gout_b,
                                             float* __restrict__ out) {
    int b0 = blockIdx.x;                           // one batch elem per CTA
    extern __shared__ float red[];                 // 4096 floats
    __shared__ __align__(16) float exc[256];
    __shared__ __align__(16) float xcat[328];      // [0:164) state, [164:328) tmp
    __shared__ __align__(16) float s1[160], s2[128], s3[128];
    __shared__ __align__(16) float buf_t[192];     // tanh pre-glu buffer (fwc / skip)
    __shared__ __align__(16) float fwc_out[192];
    __shared__ __align__(16) float gi[480], gh[480];
    __shared__ __align__(16) float g1b[160], g2b[128], g3b[128];
    __shared__ __align__(16) float skin[688];      // GRU inputs + skip_in
    __shared__ __align__(16) float skipv[128];
    __shared__ __align__(16) float pgb[4];
    __shared__ float sgain[1];
    __shared__ int   sper[1];
    int tid = threadIdx.x;
    const __half* gwh = g_wth;

    for (int i = tid; i < 256; i += NT) exc[i] = 0.0f;
    for (int i = tid; i < 328; i += NT) xcat[i] = 0.0f;
    for (int i = tid; i < 160; i += NT) s1[i] = 0.0f;
    for (int i = tid; i < 128; i += NT) { s2[i] = 0.0f; s3[i] = 0.0f; }
    __syncthreads();

    int base = 0;  // exc circular base
    for (int s = 0; s < NSTEP; s++) {
        int frame = s >> 2, sub = s & 3;
        if (tid == 0) {
            int p = period[b0 * TT + 3 + frame];
            sper[0] = min(max(p, 32), 254);
        } else if (tid == 1) {
            sgain[0] = g_gain[s * BATCH + b0];
        }
        if (tid < 164) xcat[tid] = xcat[164 + tid];
        __syncthreads();
        if (tid < 164) {
            int j = tid;
            float invg = 1.0f / (1e-5f + sgain[0]);
            float v;
            if (j < 80) {
                v = g_cond[((size_t)(b0 * TC + frame)) * 320 + sub * 80 + j];
            } else if (j < 124) {
                int i2 = j - 80;
                int idx = 254 - sper[0] + i2;
                if (idx >= 256) idx -= sper[0];
                idx = max(0, min(255, idx));
                v = exc[(base + idx) & 255] * invg;
            } else {
                v = exc[(base + 216 + (j - 124)) & 255] * invg;
            }
            xcat[164 + j] = v;
        }
        __syncthreads();

        matvec_h<328, 192, 1>(gwh + OFF_FWC, xcat, buf_t, red);
        matvec_h<192, 192, 0>(gwh + OFF_FWCG, buf_t, gh, red);
        if (tid < 192) fwc_out[tid] = buf_t[tid] * sigf(gh[tid]);
        __syncthreads();

        matvec_f<192, 4, 0>(g_wt + OFF_GOUT, fwc_out, pgb, red);
        if (tid < 4) pgb[tid] = sigf(pgb[tid] + gout_b[tid]);
        __syncthreads();

        // GRU1 input (272): [fwc_out(192) | pg0*fpitch(40) | prev(40)]
        if (tid < 272) {
            int j = tid;
            float v;
            if (j < 192) v = fwc_out[j];
            else if (j < 232) v = pgb[0] * xcat[164 + 82 + (j - 192)];
            else v = xcat[164 + 124 + (j - 232)];
            skin[j] = v;
        }
        __syncthreads();
        gru_glu<160, 272>(gwh + OFF_G1IH, gwh + OFF_G1HH, gwh + OFF_GLU1,
                          skin, s1, g1b, gi, gh, red);

        // GRU2 input (240): [g1(160) | pg1*fpitch | prev]
        if (tid < 240) {
            int j = tid;
            float v;
            if (j < 160) v = g1b[j];
            else if (j < 200) v = pgb[1] * xcat[164 + 82 + (j - 160)];
            else v = xcat[164 + 124 + (j - 200)];
            skin[j] = v;
        }
        __syncthreads();
        gru_glu<128, 240>(gwh + OFF_G2IH, gwh + OFF_G2HH, gwh + OFF_GLU2,
                          skin, s2, g2b, gi, gh, red);

        // GRU3 input (208): [g2(128) | pg2*fpitch | prev]
        if (tid < 208) {
            int j = tid;
            float v;
            if (j < 128) v = g2b[j];
            else if (j < 168) v = pgb[2] * xcat[164 + 82 + (j - 128)];
            else v = xcat[164 + 124 + (j - 168)];
            skin[j] = v;
        }
        __syncthreads();
        gru_glu<128, 208>(gwh + OFF_G3IH, gwh + OFF_G3HH, gwh + OFF_GLU3,
                          skin, s3, g3b, gi, gh, red);

        // skip_in (688): [g1 | g2 | g3 | fwc_out | pg3*fpitch | prev]
        for (int i = tid; i < 688; i += NT) {
            int j = i;
            float v;
            if (j < 160) v = g1b[j];
            else if (j < 288) v = g2b[j - 160];
            else if (j < 416) v = g3b[j - 288];
            else if (j < 608) v = fwc_out[j - 416];
            else if (j < 648) v = pgb[3] * xcat[164 + 82 + (j - 608)];
            else v = xcat[164 + 124 + (j - 648)];
            skin[j] = v;
        }
        __syncthreads();
        matvec_h<688, 128, 1>(gwh + OFF_SKIP, skin, buf_t, red);
        matvec_h<128, 128, 0>(gwh + OFF_SKIPG, buf_t, gh, red);
        if (tid < 128) skipv[tid] = buf_t[tid] * sigf(gh[tid]);
        __syncthreads();

        matvec_h<128, 40, 1>(gwh + OFF_SIG, skipv, gi, red);
        if (tid < 40) {
            float v = gi[tid] * sgain[0];
            exc[(base + tid) & 255] = v;   // becomes logical [216+tid] after base shift
            out[(size_t)b0 * 80000 + s * 40 + tid] = v;
        }
        __syncthreads();
        base = (base + 40) & 255;
    }
}

// ---------------- launch ----------------
extern "C" void kernel_launch(void* const* d_in, const int* in_sizes, int n_in,
                              void* d_out, int out_size) {
    const float* features = (const float*)d_in[0];
    const int*   period   = (const int*)d_in[1];
    const float* pembed   = (const float*)d_in[2];
    const float* fd1_w    = (const float*)d_in[3];
    const float* fconv1_w = (const float*)d_in[4];
    const float* fd2_w    = (const float*)d_in[5];
    const float* cg_w     = (const float*)d_in[6];
    const float* cg_b     = (const float*)d_in[7];
    const float* gout_b   = (const float*)d_in[23];
    float* out = (float*)d_out;

    WP wp;
    for (int i = 0; i < 15; i++) wp.p[i] = (const float*)d_in[8 + i];

    cudaFuncSetAttribute(k_convn, cudaFuncAttributeMaxDynamicSharedMemorySize, CONV_SMEM);
    cudaFuncSetAttribute(k_fd2n, cudaFuncAttributeMaxDynamicSharedMemorySize, FD2_SMEM);
    cudaFuncSetAttribute(k_scan, cudaFuncAttributeMaxDynamicSharedMemorySize, SCAN_DSMEM);

    dim3 tg((130560 + 255) / 256, 15);   // max layer elems = 480*272
    k_transpose_all<<<tg, 256>>>(wp);
    k_fd1n<<<BATCH, 256>>>(features, period, pembed, fd1_w);
    k_convn<<<dim3(BATCH, 2), 128, CONV_SMEM>>>(fconv1_w);
    k_fd2n<<<BATCH, 320, FD2_SMEM>>>(fd2_w, cg_w, cg_b);
    k_scan<<<BATCH, NT, SCAN_DSMEM>>>(period, gout_b, out);   // BPC=1, grid=128
    (void)in_sizes; (void)n_in; (void)out_size;
}